// round 1
// baseline (speedup 1.0000x reference)
#include <cuda_runtime.h>

// LocalInfoNCELoss: gather regions from f1/f2 -> p(26,576) per batch,
// normalize, Gram matrix, InfoNCE loss, mean over 16*26 rows.

#define BSZ    16
#define Hh     192
#define Ww     192
#define Cc     64
#define KKp    9
#define Rr     13
#define TWO_R  26
#define Dd     576            // 9*64
#define TAU_INV 2.0f
#define P_ROWS 28             // padded to 7 tiles of 4
#define N_TILES 7
#define N_TILE_PAIRS 28       // 7*8/2 upper-triangular incl diag

// smem layout: p[28*576] | sim[26*26] | rn[32]
#define SMEM_FLOATS (P_ROWS*Dd + TWO_R*TWO_R + 32)
#define SMEM_BYTES  (SMEM_FLOATS * 4)

__device__ float g_partial[BSZ];

__global__ __launch_bounds__(256, 1)
void infonce_batch(const float* __restrict__ f1, const float* __restrict__ f2,
                   const int* __restrict__ bi, const int* __restrict__ hi,
                   const int* __restrict__ wi)
{
    extern __shared__ float sm[];
    float* p   = sm;
    float* sim = sm + P_ROWS * Dd;
    float* rn  = sim + TWO_R * TWO_R;

    const int b    = blockIdx.x;
    const int tid  = threadIdx.x;
    const int warp = tid >> 5;
    const int lane = tid & 31;

    // ---- Phase 1: gather p rows (float4 = 16B vectorized), zero-pad rows 26,27 ----
    // row i < 13 : region i from f1 ; i >= 13 : region i-13 from f2
    // l = (r*BSZ + b)*9 + kk ;  D index = kk*64 + c
    for (int idx = tid; idx < P_ROWS * 144; idx += 256) {
        int i   = idx / 144;      // row
        int rem = idx % 144;      // float4 index within row (144*4 = 576)
        float4 val;
        if (i < TWO_R) {
            int kk = rem >> 4;          // pixel within region (0..8)
            int v  = rem & 15;          // float4 within 64-channel pixel
            int r  = (i < Rr) ? i : (i - Rr);
            const float* f = (i < Rr) ? f1 : f2;
            int l = (r * BSZ + b) * KKp + kk;
            long off = (((long)bi[l] * Hh + hi[l]) * Ww + wi[l]) * Cc + v * 4;
            val = *(const float4*)(f + off);
        } else {
            val = make_float4(0.f, 0.f, 0.f, 0.f);
        }
        ((float4*)(p + i * Dd))[rem] = val;
    }
    __syncthreads();

    // ---- Phase 2: raw Gram, 4x4 register-tiled, warp per tile pair ----
    for (int t = warp; t < N_TILE_PAIRS; t += 8) {
        int ti = 0, tt = t;
        while (tt >= N_TILES - ti) { tt -= N_TILES - ti; ti++; }
        int tj = ti + tt;   // tj >= ti

        const float* pa = p + (ti * 4) * Dd;
        const float* pb = p + (tj * 4) * Dd;
        float acc[4][4];
        #pragma unroll
        for (int a = 0; a < 4; a++)
            #pragma unroll
            for (int c2 = 0; c2 < 4; c2++) acc[a][c2] = 0.f;

        for (int d = lane; d < Dd; d += 32) {
            float av[4], bv[4];
            #pragma unroll
            for (int a = 0; a < 4; a++)  av[a]  = pa[a * Dd + d];
            #pragma unroll
            for (int c2 = 0; c2 < 4; c2++) bv[c2] = pb[c2 * Dd + d];
            #pragma unroll
            for (int a = 0; a < 4; a++)
                #pragma unroll
                for (int c2 = 0; c2 < 4; c2++)
                    acc[a][c2] = fmaf(av[a], bv[c2], acc[a][c2]);
        }
        #pragma unroll
        for (int a = 0; a < 4; a++) {
            #pragma unroll
            for (int c2 = 0; c2 < 4; c2++) {
                float v = acc[a][c2];
                #pragma unroll
                for (int o = 16; o > 0; o >>= 1)
                    v += __shfl_down_sync(0xffffffffu, v, o);
                if (lane == 0) {
                    int i = ti * 4 + a, j = tj * 4 + c2;
                    if (i < TWO_R && j < TWO_R) {
                        sim[i * TWO_R + j] = v;
                        sim[j * TWO_R + i] = v;
                    }
                }
            }
        }
    }
    __syncthreads();

    // ---- Phase 3: norms from Gram diagonal ----
    if (tid < TWO_R) {
        float n = sqrtf(sim[tid * TWO_R + tid]);
        rn[tid] = 1.0f / fmaxf(n, 1e-8f);
    }
    __syncthreads();

    // ---- Phase 4: scale sim = G_ij * rn_i * rn_j / tau ----
    for (int idx = tid; idx < TWO_R * TWO_R; idx += 256) {
        int i = idx / TWO_R, j = idx % TWO_R;
        sim[idx] = sim[idx] * rn[i] * rn[j] * TAU_INV;
    }
    __syncthreads();

    // ---- Phase 5: per-row loss = logsumexp_{j!=i}(sim_ij) - sim[i][partner] ----
    if (warp == 0) {
        float loss = 0.f;
        if (lane < TWO_R) {
            int i = lane;
            const float* row = sim + i * TWO_R;
            float m = -1e30f;
            for (int j = 0; j < TWO_R; j++)
                if (j != i) m = fmaxf(m, row[j]);
            float s = 0.f;
            for (int j = 0; j < TWO_R; j++)
                if (j != i) s += expf(row[j] - m);
            int partner = (i + Rr) % TWO_R;
            loss = logf(s) + m - row[partner];
        }
        #pragma unroll
        for (int o = 16; o > 0; o >>= 1)
            loss += __shfl_down_sync(0xffffffffu, loss, o);
        if (lane == 0) g_partial[b] = loss;
    }
}

__global__ void infonce_final(float* __restrict__ out)
{
    int lane = threadIdx.x;
    float v = (lane < BSZ) ? g_partial[lane] : 0.f;
    #pragma unroll
    for (int o = 16; o > 0; o >>= 1)
        v += __shfl_down_sync(0xffffffffu, v, o);
    if (lane == 0) out[0] = v / (float)(BSZ * TWO_R);
}

extern "C" void kernel_launch(void* const* d_in, const int* in_sizes, int n_in,
                              void* d_out, int out_size)
{
    const float* f1 = (const float*)d_in[0];
    const float* f2 = (const float*)d_in[1];
    const int*   bi = (const int*)d_in[2];
    const int*   hi = (const int*)d_in[3];
    const int*   wi = (const int*)d_in[4];
    float* out = (float*)d_out;

    cudaFuncSetAttribute(infonce_batch,
                         cudaFuncAttributeMaxDynamicSharedMemorySize, SMEM_BYTES);

    infonce_batch<<<BSZ, 256, SMEM_BYTES>>>(f1, f2, bi, hi, wi);
    infonce_final<<<1, 32>>>(out);
}

// round 3
// speedup vs baseline: 1.3977x; 1.3977x over previous
#include <cuda_runtime.h>

// LocalInfoNCELoss fused single-kernel version:
// gather -> Gram -> normalize -> InfoNCE -> cross-block reduce -> out[0]

#define BSZ    16
#define Hh     192
#define Ww     192
#define Cc     64
#define KKp    9
#define Rr     13
#define TWO_R  26
#define Dd     576            // 9*64
#define TAU_INV 2.0f
#define P_ROWS 28             // padded to 7 tiles of 4
#define N_TILES 7
#define N_TILE_PAIRS 28       // 7*8/2 upper-triangular incl diag
#define N_OFF (TWO_R * KKp)   // 234 staged base offsets

// smem layout: p[28*576] | sim[26*26] | rn[32] | off[234] (long)
#define SMEM_FLOATS (P_ROWS*Dd + TWO_R*TWO_R + 32)
#define SMEM_BYTES  (SMEM_FLOATS * 4 + N_OFF * 8)

__device__ float    g_partial[BSZ];
__device__ unsigned g_count = 0;

__global__ __launch_bounds__(256, 1)
void infonce_fused(const float* __restrict__ f1, const float* __restrict__ f2,
                   const int* __restrict__ bi, const int* __restrict__ hi,
                   const int* __restrict__ wi, float* __restrict__ out)
{
    extern __shared__ float sm[];
    float* p   = sm;
    float* sim = sm + P_ROWS * Dd;
    float* rn  = sim + TWO_R * TWO_R;
    long*  off = (long*)(rn + 32);

    const int b    = blockIdx.x;
    const int tid  = threadIdx.x;
    const int warp = tid >> 5;
    const int lane = tid & 31;

    // ---- Phase 0: stage base element-offsets for all 26 rows x 9 pixels ----
    // row i < 13: region i from f1 ; i >= 13: region i-13 from f2 (resolved later)
    if (tid < N_OFF) {
        int i  = tid / KKp;               // p row 0..25
        int kk = tid - i * KKp;           // pixel 0..8
        int r  = (i < Rr) ? i : (i - Rr);
        int l  = (r * BSZ + b) * KKp + kk;
        off[tid] = (((long)bi[l] * Hh + hi[l]) * Ww + wi[l]) * Cc;
    }
    __syncthreads();

    // ---- Phase 1: gather p rows (float4 vectorized), zero-pad rows 26,27 ----
    #pragma unroll 4
    for (int idx = tid; idx < P_ROWS * 144; idx += 256) {
        int i   = idx / 144;      // row
        int rem = idx - i * 144;  // float4 index within row
        float4 val;
        if (i < TWO_R) {
            int kk = rem >> 4;          // pixel within region (0..8)
            int v  = rem & 15;          // float4 within 64-channel pixel
            const float* f = (i < Rr) ? f1 : f2;
            val = *(const float4*)(f + off[i * KKp + kk] + v * 4);
        } else {
            val = make_float4(0.f, 0.f, 0.f, 0.f);
        }
        ((float4*)(p + i * Dd))[rem] = val;
    }
    __syncthreads();

    // ---- Phase 2: raw Gram, 4x4 register-tiled, warp per tile pair ----
    for (int t = warp; t < N_TILE_PAIRS; t += 8) {
        int ti = 0, tt = t;
        while (tt >= N_TILES - ti) { tt -= N_TILES - ti; ti++; }
        int tj = ti + tt;   // tj >= ti

        const float* pa = p + (ti * 4) * Dd;
        const float* pb = p + (tj * 4) * Dd;
        float acc[4][4];
        #pragma unroll
        for (int a = 0; a < 4; a++)
            #pragma unroll
            for (int c2 = 0; c2 < 4; c2++) acc[a][c2] = 0.f;

        #pragma unroll 2
        for (int d = lane; d < Dd; d += 32) {
            float av[4], bv[4];
            #pragma unroll
            for (int a = 0; a < 4; a++)  av[a]  = pa[a * Dd + d];
            #pragma unroll
            for (int c2 = 0; c2 < 4; c2++) bv[c2] = pb[c2 * Dd + d];
            #pragma unroll
            for (int a = 0; a < 4; a++)
                #pragma unroll
                for (int c2 = 0; c2 < 4; c2++)
                    acc[a][c2] = fmaf(av[a], bv[c2], acc[a][c2]);
        }
        #pragma unroll
        for (int a = 0; a < 4; a++) {
            #pragma unroll
            for (int c2 = 0; c2 < 4; c2++) {
                float v = acc[a][c2];
                #pragma unroll
                for (int o = 16; o > 0; o >>= 1)
                    v += __shfl_down_sync(0xffffffffu, v, o);
                if (lane == 0) {
                    int i = ti * 4 + a, j = tj * 4 + c2;
                    if (i < TWO_R && j < TWO_R) {
                        sim[i * TWO_R + j] = v;
                        sim[j * TWO_R + i] = v;
                    }
                }
            }
        }
    }
    __syncthreads();

    // ---- Phase 3: reciprocal norms from Gram diagonal ----
    if (tid < TWO_R) {
        float n = sqrtf(sim[tid * TWO_R + tid]);
        rn[tid] = 1.0f / fmaxf(n, 1e-8f);
    }
    __syncthreads();

    // ---- Phase 4: sim = G_ij * rn_i * rn_j / tau ----
    for (int idx = tid; idx < TWO_R * TWO_R; idx += 256) {
        int i = idx / TWO_R, j = idx - i * TWO_R;
        sim[idx] = sim[idx] * rn[i] * rn[j] * TAU_INV;
    }
    __syncthreads();

    // ---- Phase 5: per-row loss + cross-block reduce (threadfence pattern) ----
    if (warp == 0) {
        float loss = 0.f;
        if (lane < TWO_R) {
            int i = lane;
            const float* row = sim + i * TWO_R;
            float m = -1e30f;
            #pragma unroll
            for (int j = 0; j < TWO_R; j++)
                if (j != i) m = fmaxf(m, row[j]);
            float s = 0.f;
            #pragma unroll
            for (int j = 0; j < TWO_R; j++)
                if (j != i) s += __expf(row[j] - m);
            int partner = (i + Rr) % TWO_R;
            loss = __logf(s) + m - row[partner];
        }
        #pragma unroll
        for (int o = 16; o > 0; o >>= 1)
            loss += __shfl_down_sync(0xffffffffu, loss, o);

        if (lane == 0) {
            g_partial[b] = loss;
            __threadfence();
            unsigned prev = atomicAdd(&g_count, 1u);
            if (prev == BSZ - 1) {
                // last block: final reduction, write output, reset counter
                float total = 0.f;
                #pragma unroll
                for (int k = 0; k < BSZ; k++) total += g_partial[k];
                out[0] = total / (float)(BSZ * TWO_R);
                g_count = 0;
            }
        }
    }
}

extern "C" void kernel_launch(void* const* d_in, const int* in_sizes, int n_in,
                              void* d_out, int out_size)
{
    const float* f1 = (const float*)d_in[0];
    const float* f2 = (const float*)d_in[1];
    const int*   bi = (const int*)d_in[2];
    const int*   hi = (const int*)d_in[3];
    const int*   wi = (const int*)d_in[4];
    float* out = (float*)d_out;

    cudaFuncSetAttribute(infonce_fused,
                         cudaFuncAttributeMaxDynamicSharedMemorySize, SMEM_BYTES);

    infonce_fused<<<BSZ, 256, SMEM_BYTES>>>(f1, f2, bi, hi, wi, out);
}

// round 4
// speedup vs baseline: 1.8450x; 1.3200x over previous
#include <cuda_runtime.h>

// LocalInfoNCELoss, split-D version:
// grid = 16 batches x 9 pixel-slices = 144 blocks (one wave on 148 SMs).
// Each block: gather 26x64 slice -> partial Gram -> atomicAdd to global.
// 9th block per batch: softmax + row losses. 16th batch: final output + reset.

#define BSZ    16
#define Hh     192
#define Ww     192
#define Cc     64
#define KKp    9
#define Rr     13
#define TWO_R  26
#define TAU_INV 2.0f
#define NPIX   9
#define N_TILES 7
#define N_TILE_PAIRS 28

__device__ float    g_sim[BSZ][TWO_R * TWO_R];   // zero-init, reset each run
__device__ unsigned g_cnt[BSZ];
__device__ float    g_loss;
__device__ unsigned g_done;

__global__ __launch_bounds__(256, 1)
void infonce_split(const float* __restrict__ f1, const float* __restrict__ f2,
                   const int* __restrict__ bi, const int* __restrict__ hi,
                   const int* __restrict__ wi, float* __restrict__ out)
{
    __shared__ float p[28][Cc];            // 26 rows + 2 zero-pad rows
    __shared__ float sim[TWO_R * TWO_R];
    __shared__ float rn[32];
    __shared__ float rowloss[8];
    __shared__ int   off[TWO_R];
    __shared__ int   s_last;

    const int blk  = blockIdx.x;
    const int b    = blk / NPIX;
    const int s    = blk - b * NPIX;       // pixel slice 0..8
    const int tid  = threadIdx.x;
    const int warp = tid >> 5;
    const int lane = tid & 31;

    // ---- Phase 0: 26 base offsets for this pixel slice ----
    if (tid < TWO_R) {
        int r = (tid < Rr) ? tid : tid - Rr;
        int l = (r * BSZ + b) * KKp + s;
        off[tid] = ((bi[l] * Hh + hi[l]) * Ww + wi[l]) * Cc;
    }
    if (tid >= 224) {  // 32 threads zero pad rows 26,27 (32 float4)
        int z = tid - 224;
        ((float4*)p[26])[z] = make_float4(0.f, 0.f, 0.f, 0.f);
    }
    __syncthreads();

    // ---- Phase 1: gather 26 rows x 16 float4 ----
    for (int idx = tid; idx < TWO_R * 16; idx += 256) {
        int i = idx >> 4, v = idx & 15;
        const float* f = (i < Rr) ? f1 : f2;
        ((float4*)p[i])[v] = *(const float4*)(f + off[i] + v * 4);
    }
    __syncthreads();

    // ---- Phase 2: partial Gram (D=64), 4x4 register tiles, warp per pair ----
    for (int t = warp; t < N_TILE_PAIRS; t += 8) {
        int ti = 0, tt = t;
        while (tt >= N_TILES - ti) { tt -= N_TILES - ti; ti++; }
        int tj = ti + tt;

        float acc[4][4];
        #pragma unroll
        for (int a = 0; a < 4; a++)
            #pragma unroll
            for (int c = 0; c < 4; c++) acc[a][c] = 0.f;

        #pragma unroll
        for (int it = 0; it < 2; it++) {
            int d = lane + it * 32;
            float av[4], bv[4];
            #pragma unroll
            for (int a = 0; a < 4; a++) av[a] = p[ti * 4 + a][d];
            #pragma unroll
            for (int c = 0; c < 4; c++) bv[c] = p[tj * 4 + c][d];
            #pragma unroll
            for (int a = 0; a < 4; a++)
                #pragma unroll
                for (int c = 0; c < 4; c++)
                    acc[a][c] = fmaf(av[a], bv[c], acc[a][c]);
        }
        #pragma unroll
        for (int a = 0; a < 4; a++) {
            #pragma unroll
            for (int c = 0; c < 4; c++) {
                float v = acc[a][c];
                #pragma unroll
                for (int o = 16; o > 0; o >>= 1)
                    v += __shfl_down_sync(0xffffffffu, v, o);
                if (lane == 0) {
                    int i = ti * 4 + a, j = tj * 4 + c;
                    if (i < TWO_R && j < TWO_R) {
                        sim[i * TWO_R + j] = v;
                        sim[j * TWO_R + i] = v;
                    }
                }
            }
        }
    }
    __syncthreads();

    // ---- Phase 3: accumulate into global per-batch Gram ----
    for (int e = tid; e < TWO_R * TWO_R; e += 256)
        atomicAdd(&g_sim[b][e], sim[e]);
    __threadfence();
    __syncthreads();
    if (tid == 0)
        s_last = (atomicAdd(&g_cnt[b], 1u) == NPIX - 1);
    __syncthreads();
    if (!s_last) return;

    // ---- Batch-last block: load full Gram, reset state ----
    for (int e = tid; e < TWO_R * TWO_R; e += 256)
        sim[e] = __ldcg(&g_sim[b][e]);
    __syncthreads();
    for (int e = tid; e < TWO_R * TWO_R; e += 256)
        g_sim[b][e] = 0.f;
    if (tid == 0) g_cnt[b] = 0;
    if (tid < TWO_R)
        rn[tid] = 1.f / fmaxf(sqrtf(sim[tid * TWO_R + tid]), 1e-8f);
    __syncthreads();

    // ---- Phase 4: per-row losses, warp per row (lane-parallel over j) ----
    float wl = 0.f;
    for (int i = warp; i < TWO_R; i += 8) {
        bool valid = (lane < TWO_R) && (lane != i);
        float v = valid ? sim[i * TWO_R + lane] * rn[i] * rn[lane] * TAU_INV
                        : -1e30f;
        float m = v;
        #pragma unroll
        for (int o = 16; o > 0; o >>= 1)
            m = fmaxf(m, __shfl_xor_sync(0xffffffffu, m, o));
        float e = valid ? __expf(v - m) : 0.f;
        #pragma unroll
        for (int o = 16; o > 0; o >>= 1)
            e += __shfl_xor_sync(0xffffffffu, e, o);
        int partner = (i + Rr) % TWO_R;
        float pv = __shfl_sync(0xffffffffu, v, partner);
        if (lane == 0) wl += __logf(e) + m - pv;
    }
    if (lane == 0) rowloss[warp] = wl;
    __syncthreads();

    // ---- Phase 5: batch loss -> global; 16th batch writes out & resets ----
    if (tid == 0) {
        float total = 0.f;
        #pragma unroll
        for (int k = 0; k < 8; k++) total += rowloss[k];
        atomicAdd(&g_loss, total);
        __threadfence();
        if (atomicAdd(&g_done, 1u) == BSZ - 1) {
            float tl = atomicAdd(&g_loss, 0.f);   // full sum (all adds fenced)
            out[0] = tl / (float)(BSZ * TWO_R);
            g_loss = 0.f;
            g_done = 0;
        }
    }
}

extern "C" void kernel_launch(void* const* d_in, const int* in_sizes, int n_in,
                              void* d_out, int out_size)
{
    const float* f1 = (const float*)d_in[0];
    const float* f2 = (const float*)d_in[1];
    const int*   bi = (const int*)d_in[2];
    const int*   hi = (const int*)d_in[3];
    const int*   wi = (const int*)d_in[4];
    float* out = (float*)d_out;

    infonce_split<<<BSZ * NPIX, 256>>>(f1, f2, bi, hi, wi, out);
}